// round 7
// baseline (speedup 1.0000x reference)
#include <cuda_runtime.h>

#define Bq   64
#define NPG  501
#define NN   (Bq * NPG)        // 32064
#define HID  128
#define LMD  1024
#define NREL 42
#define EMAX 520001
#define NPAD (NN + 128)

// ---------------- packed f32x2 helpers (Blackwell FFMA2) ----------------
__device__ __forceinline__ void ffma2(unsigned long long& acc,
                                      unsigned long long a, unsigned long long b) {
    asm("fma.rn.f32x2 %0, %1, %2, %0;" : "+l"(acc) : "l"(a), "l"(b));
}
__device__ __forceinline__ unsigned long long pack2(float x) {
    unsigned long long r;
    asm("mov.b64 %0, {%1, %1};" : "=l"(r) : "f"(x));
    return r;
}
__device__ __forceinline__ float2 unpack2(unsigned long long v) {
    float2 f;
    asm("mov.b64 {%0, %1}, %2;" : "=f"(f.x), "=f"(f.y) : "l"(v));
    return f;
}

// ---------------- scratch (device globals; no allocs) ----------------
__device__ int   g_src[EMAX];
__device__ int   g_dst[EMAX];
__device__ int   g_etype[EMAX];
__device__ int   g_ctxn[Bq];
__device__ float g_ctx[Bq * HID];
__device__ float g_tdot[NREL];
__device__ float g_tmpT[Bq * HID * HID];      // [b][h][k]
__device__ float g_x[NPAD * HID];
__device__ float g_nodes[NPAD * HID];
__device__ float g_xl[NPAD * HID];
__device__ float g_as[NPAD];
__device__ float g_ad[NPAD];
__device__ float g_loop[NN];
__device__ int   g_deg[NN];
__device__ int   g_off[NN + 1];
__device__ int   g_pos[NN];
__device__ int   g_csrc[EMAX];
__device__ float g_cae[EMAX];
// active-set pruning
__device__ int   g_isctx[NN];
__device__ int   g_m3[NN];
__device__ int   g_m2[NN];
__device__ int   g_list2[NN];
__device__ int   g_list3[NN];
__device__ int   g_cnt2;
__device__ int   g_cnt3;

// zero scratch + copy node_emb -> g_x (vectorized)
__global__ void k_init(const float* __restrict__ ne) {
    int i = blockIdx.x * blockDim.x + threadIdx.x;
    int stride = gridDim.x * blockDim.x;
    const float4* s4 = (const float4*)ne;
    float4* d4 = (float4*)g_x;
    for (int j = i; j < NN * HID / 4; j += stride) d4[j] = s4[j];
    for (int j = i; j < NN; j += stride) {
        g_deg[j] = 0; g_isctx[j] = 0; g_m3[j] = 0; g_m2[j] = 0;
    }
    if (i == 0) { g_cnt2 = 0; g_cnt3 = 0; }
}

// cvt (dtype-flexible) + degree atomics + ctx marks, all in one pass
__global__ void k_cvt(const void* __restrict__ ei, const void* __restrict__ et,
                      const void* __restrict__ ctxn, int E) {
    int i = blockIdx.x * blockDim.x + threadIdx.x;
    bool is64 = (((const int*)ctxn)[1] == 0);
    if (i < E) {
        int s, d, t;
        if (is64) {
            s = (int)((const long long*)ei)[i];
            d = (int)((const long long*)ei)[E + i];
            t = (int)((const long long*)et)[i];
        } else {
            s = ((const int*)ei)[i];
            d = ((const int*)ei)[E + i];
            t = ((const int*)et)[i];
        }
        g_src[i] = s; g_dst[i] = d; g_etype[i] = t;
        atomicAdd(&g_deg[d], 1);
    }
    if (i < Bq) {
        int n = is64 ? (int)((const long long*)ctxn)[i] : ((const int*)ctxn)[i];
        g_ctxn[i] = n;
        g_isctx[n] = 1;
        g_m3[n] = 1;
    }
}

// v_edge = W_edge@att_edge; table_dot (MUST precede k_fill)
__global__ void k_prep(const float* __restrict__ We, const float* __restrict__ ae,
                       const float* __restrict__ tab) {
    __shared__ float sv[HID];
    int t = threadIdx.x;
    float acc = 0.f;
    for (int j = 0; j < HID; j++) acc += We[t * HID + j] * ae[j];
    sv[t] = acc;
    __syncthreads();
    if (t < NREL) {
        float a2 = 0.f;
        for (int j = 0; j < HID; j++) a2 += tab[t * HID + j] * sv[j];
        g_tdot[t] = a2;
    }
}

// tmpT[b][h][k] = sum_l lm[b,l]*W_bil[k,l,h]  — packed f32x2
// grid (128 k, 2 h-halves); 256 thr: tr=t>>3 -> 2 b rows, tc=t&7 -> 8 h cols
__global__ void __launch_bounds__(256) k_tmpp(const float* __restrict__ lm,
                                              const float* __restrict__ Wb) {
    int k = blockIdx.x;
    int h0 = blockIdx.y * 64;
    int t = threadIdx.x;
    int b0 = (t >> 3) * 2;
    int hc = h0 + (t & 7) * 8;
    const float* Wk = Wb + (size_t)k * LMD * HID;

    unsigned long long acc2[2][4];
#pragma unroll
    for (int i = 0; i < 2; i++)
#pragma unroll
        for (int p = 0; p < 4; p++) acc2[i][p] = 0ull;

#pragma unroll 2
    for (int l = 0; l < LMD; l += 4) {
        float4 a0 = *(const float4*)&lm[(size_t)b0 * LMD + l];
        float4 a1 = *(const float4*)&lm[(size_t)(b0 + 1) * LMD + l];
#pragma unroll
        for (int u = 0; u < 4; u++) {
            ulonglong2 w01 = *(const ulonglong2*)&Wk[(size_t)(l + u) * HID + hc];
            ulonglong2 w23 = *(const ulonglong2*)&Wk[(size_t)(l + u) * HID + hc + 4];
            float va0 = (u == 0) ? a0.x : (u == 1) ? a0.y : (u == 2) ? a0.z : a0.w;
            float va1 = (u == 0) ? a1.x : (u == 1) ? a1.y : (u == 2) ? a1.z : a1.w;
            unsigned long long p0 = pack2(va0);
            unsigned long long p1 = pack2(va1);
            ffma2(acc2[0][0], p0, w01.x); ffma2(acc2[0][1], p0, w01.y);
            ffma2(acc2[0][2], p0, w23.x); ffma2(acc2[0][3], p0, w23.y);
            ffma2(acc2[1][0], p1, w01.x); ffma2(acc2[1][1], p1, w01.y);
            ffma2(acc2[1][2], p1, w23.x); ffma2(acc2[1][3], p1, w23.y);
        }
    }
#pragma unroll
    for (int i = 0; i < 2; i++)
#pragma unroll
        for (int p = 0; p < 4; p++) {
            float2 f = unpack2(acc2[i][p]);
            size_t base = (size_t)(b0 + i) * HID * HID + (size_t)(hc + 2 * p) * HID + k;
            g_tmpT[base] = f.x;
            g_tmpT[base + HID] = f.y;
        }
}

__global__ void k_mark3(int E) {
    int i = blockIdx.x * blockDim.x + threadIdx.x;
    if (i < E && g_isctx[g_dst[i]]) g_m3[g_src[i]] = 1;
}

__global__ void k_mark2(int E) {
    int i = blockIdx.x * blockDim.x + threadIdx.x;
    if (i < E && g_m3[g_dst[i]]) g_m2[g_src[i]] = 1;
}

// single-block exclusive scan over g_deg -> g_off, g_pos
__global__ void k_scan() {
    __shared__ int sp[1024];
    int t = threadIdx.x;
    int base = t * 32;
    int loc[32];
    int s = 0;
#pragma unroll
    for (int i = 0; i < 32; i++) {
        int idx = base + i;
        int v = (idx < NN) ? g_deg[idx] : 0;
        loc[i] = s;
        s += v;
    }
    sp[t] = s;
    __syncthreads();
    for (int d = 1; d < 1024; d <<= 1) {
        int v = (t >= d) ? sp[t - d] : 0;
        __syncthreads();
        sp[t] += v;
        __syncthreads();
    }
    int chunk = (t == 0) ? 0 : sp[t - 1];
#pragma unroll
    for (int i = 0; i < 32; i++) {
        int idx = base + i;
        if (idx < NN) {
            int o = chunk + loc[i];
            g_off[idx] = o;
            g_pos[idx] = o;
        }
    }
    if (t == 1023) g_off[NN] = sp[1023];
}

__global__ void k_fill(int E) {
    int i = blockIdx.x * blockDim.x + threadIdx.x;
    if (i < E) {
        int d = g_dst[i];
        int p = atomicAdd(&g_pos[d], 1);
        g_csrc[p] = g_src[i];
        g_cae[p] = g_tdot[g_etype[i]];
    }
}

__global__ void k_compact() {
    int n = blockIdx.x * blockDim.x + threadIdx.x;
    if (n >= NN) return;
    int in3 = g_m3[n];
    int in2 = g_m2[n] | in3;
    if (in3) g_list3[atomicAdd(&g_cnt3, 1)] = n;
    if (in2) g_list2[atomicAdd(&g_cnt2, 1)] = n;
}

// self-loop attention bias = mean of incoming table_dot
__global__ void k_loopdot() {
    int w = (blockIdx.x * blockDim.x + threadIdx.x) >> 5;
    int lane = threadIdx.x & 31;
    if (w >= NN) return;
    int s = g_off[w], e = g_off[w + 1];
    float acc = 0.f;
    for (int i = s + lane; i < e; i += 32) acc += g_cae[i];
    for (int o = 16; o; o >>= 1) acc += __shfl_xor_sync(0xffffffffu, acc, o);
    if (lane == 0) {
        int d = e - s;
        g_loop[w] = d ? acc / (float)d : 0.f;
    }
}

// ctx_emb = lm @ W_lm + b_lm ; writes g_ctx and ctx rows of g_x
__global__ void __launch_bounds__(1024) k_ctx(const float* __restrict__ lm,
                                              const float* __restrict__ W,
                                              const float* __restrict__ bl) {
    __shared__ float red[1024];
    int b = blockIdx.x, t = threadIdx.x;
    int c = t & 127, lg = t >> 7;
    const float* l0 = lm + (size_t)b * LMD + lg * 128;
    const float* Wp = W + (size_t)(lg * 128) * HID + c;
    float a0 = 0.f, a1 = 0.f;
#pragma unroll 8
    for (int l = 0; l < 128; l += 2) {
        a0 += l0[l] * Wp[(size_t)l * HID];
        a1 += l0[l + 1] * Wp[(size_t)(l + 1) * HID];
    }
    red[t] = a0 + a1;
    __syncthreads();
    for (int s = 512; s >= 128; s >>= 1) {
        if (t < s) red[t] += red[t + s];
        __syncthreads();
    }
    if (t < 128) {
        float v = red[t] + bl[t];
        g_ctx[b * HID + t] = v;
        g_x[(size_t)g_ctxn[b] * HID + t] = v;
    }
}

// ===== packed f32x2 GEMM: 64-row block, 4x8 tile/thread =====
// mode 0: A=g_x(+b*NPG*HID), B=g_tmpT[b], C=g_nodes(+...), +bias
// mode 1: A=g_nodes, B=Bext(W_gat), C=g_xl, + att_src/att_dst row dots
__global__ void __launch_bounds__(256) k_gemmp(int mode, const float* __restrict__ Bext,
                                               int M, int sA,
                                               const float* __restrict__ bias,
                                               const float* __restrict__ atts,
                                               const float* __restrict__ attd) {
    __shared__ float Bs[64 * 128];      // 32 KB (K staged in 2 chunks)
    const float* A = mode ? g_nodes : g_x;
    float* C = mode ? g_xl : g_nodes;
    const float* Bm = mode ? Bext : (g_tmpT + (size_t)blockIdx.y * HID * HID);
    A += (size_t)blockIdx.y * sA;
    C += (size_t)blockIdx.y * sA;

    const int t = threadIdx.x;
    const int tc = t & 15, tr = t >> 4;
    const int r0 = blockIdx.x * 64 + tr * 4;    // 4 rows
    const int c0 = tc * 8;                      // 8 cols (4 f32x2 pairs)

    unsigned long long acc2[4][4];
#pragma unroll
    for (int i = 0; i < 4; i++)
#pragma unroll
        for (int p = 0; p < 4; p++) acc2[i][p] = 0ull;

#pragma unroll
    for (int hb = 0; hb < 2; hb++) {
        {
            const float4* src = (const float4*)(Bm + hb * 64 * HID);
            float4* dst = (float4*)Bs;
#pragma unroll
            for (int j = 0; j < 8; j++) dst[t + j * 256] = src[t + j * 256];
        }
        __syncthreads();

#pragma unroll 2
        for (int h4 = 0; h4 < 16; h4++) {
            float4 av[4];
#pragma unroll
            for (int i = 0; i < 4; i++)
                av[i] = *(const float4*)&A[(size_t)(r0 + i) * HID + hb * 64 + h4 * 4];
#pragma unroll
            for (int u = 0; u < 4; u++) {
                ulonglong2 b01 = *(const ulonglong2*)&Bs[(h4 * 4 + u) * 128 + c0];
                ulonglong2 b23 = *(const ulonglong2*)&Bs[(h4 * 4 + u) * 128 + c0 + 4];
#pragma unroll
                for (int i = 0; i < 4; i++) {
                    float a = (u == 0) ? av[i].x : (u == 1) ? av[i].y
                            : (u == 2) ? av[i].z : av[i].w;
                    unsigned long long a2 = pack2(a);
                    ffma2(acc2[i][0], a2, b01.x);
                    ffma2(acc2[i][1], a2, b01.y);
                    ffma2(acc2[i][2], a2, b23.x);
                    ffma2(acc2[i][3], a2, b23.y);
                }
            }
        }
        __syncthreads();
    }

    // unpack accumulators
    float accf[4][8];
#pragma unroll
    for (int i = 0; i < 4; i++)
#pragma unroll
        for (int p = 0; p < 4; p++) {
            float2 f = unpack2(acc2[i][p]);
            accf[i][2 * p] = f.x;
            accf[i][2 * p + 1] = f.y;
        }

    float4 bs0 = {0, 0, 0, 0}, bs1 = {0, 0, 0, 0};
    if (bias) {
        bs0 = *(const float4*)&bias[c0];
        bs1 = *(const float4*)&bias[c0 + 4];
    }
#pragma unroll
    for (int i = 0; i < 4; i++) {
        int m = r0 + i;
        if (m < M) {
            float4 w0, w1;
            w0.x = accf[i][0] + bs0.x; w0.y = accf[i][1] + bs0.y;
            w0.z = accf[i][2] + bs0.z; w0.w = accf[i][3] + bs0.w;
            w1.x = accf[i][4] + bs1.x; w1.y = accf[i][5] + bs1.y;
            w1.z = accf[i][6] + bs1.z; w1.w = accf[i][7] + bs1.w;
            *(float4*)&C[(size_t)m * HID + c0] = w0;
            *(float4*)&C[(size_t)m * HID + c0 + 4] = w1;
        }
    }

    if (atts) {
        float4 sa0 = *(const float4*)&atts[c0];
        float4 sa1 = *(const float4*)&atts[c0 + 4];
        float4 da0 = *(const float4*)&attd[c0];
        float4 da1 = *(const float4*)&attd[c0 + 4];
#pragma unroll
        for (int i = 0; i < 4; i++) {
            float ps = accf[i][0] * sa0.x + accf[i][1] * sa0.y + accf[i][2] * sa0.z + accf[i][3] * sa0.w
                     + accf[i][4] * sa1.x + accf[i][5] * sa1.y + accf[i][6] * sa1.z + accf[i][7] * sa1.w;
            float pd = accf[i][0] * da0.x + accf[i][1] * da0.y + accf[i][2] * da0.z + accf[i][3] * da0.w
                     + accf[i][4] * da1.x + accf[i][5] * da1.y + accf[i][6] * da1.z + accf[i][7] * da1.w;
            for (int o = 8; o; o >>= 1) {
                ps += __shfl_down_sync(0xffffffffu, ps, o, 16);
                pd += __shfl_down_sync(0xffffffffu, pd, o, 16);
            }
            int m = r0 + i;
            if (tc == 0 && m < M) { g_as[m] = ps; g_ad[m] = pd; }
        }
    }
}

// 32-row list-indirected GEMM: rows from g_list2 (0) / g_list3 (1)
__global__ void __launch_bounds__(256) k_gemml(int lsel, const float* __restrict__ Bm,
                                               const float* __restrict__ atts,
                                               const float* __restrict__ attd) {
    int cnt = lsel ? g_cnt3 : g_cnt2;
    if (blockIdx.x * 32 >= cnt) return;
    const int* list = lsel ? g_list3 : g_list2;

    int t = threadIdx.x;
    int rg = t >> 3, cg = t & 7;
    int m = blockIdx.x * 32 + rg;
    int k0 = cg * 16;

    bool ok = m < cnt;
    int row = ok ? list[m] : list[0];

    float acc[16];
#pragma unroll
    for (int j = 0; j < 16; j++) acc[j] = 0.f;

    for (int h = 0; h < HID; h += 4) {
        float4 v = *(const float4*)&g_nodes[(size_t)row * HID + h];
        float a[4] = {v.x, v.y, v.z, v.w};
#pragma unroll
        for (int u = 0; u < 4; u++) {
            float br[16];
#pragma unroll
            for (int q = 0; q < 4; q++) {
                float4 w = *(const float4*)&Bm[(size_t)(h + u) * HID + k0 + q * 4];
                br[q * 4 + 0] = w.x; br[q * 4 + 1] = w.y;
                br[q * 4 + 2] = w.z; br[q * 4 + 3] = w.w;
            }
            float av = a[u];
#pragma unroll
            for (int j = 0; j < 16; j++) acc[j] += av * br[j];
        }
    }

    if (ok) {
#pragma unroll
        for (int q = 0; q < 4; q++) {
            float4 w;
            w.x = acc[q * 4 + 0]; w.y = acc[q * 4 + 1];
            w.z = acc[q * 4 + 2]; w.w = acc[q * 4 + 3];
            *(float4*)&g_xl[(size_t)row * HID + k0 + q * 4] = w;
        }
    }

    float ps = 0.f, pd = 0.f;
#pragma unroll
    for (int q = 0; q < 4; q++) {
        float4 w = *(const float4*)&atts[k0 + q * 4];
        float4 u = *(const float4*)&attd[k0 + q * 4];
        ps += acc[q * 4 + 0] * w.x + acc[q * 4 + 1] * w.y + acc[q * 4 + 2] * w.z + acc[q * 4 + 3] * w.w;
        pd += acc[q * 4 + 0] * u.x + acc[q * 4 + 1] * u.y + acc[q * 4 + 2] * u.z + acc[q * 4 + 3] * u.w;
    }
    for (int o = 4; o; o >>= 1) {
        ps += __shfl_down_sync(0xffffffffu, ps, o, 8);
        pd += __shfl_down_sync(0xffffffffu, pd, o, 8);
    }
    if (cg == 0 && ok) { g_as[row] = ps; g_ad[row] = pd; }
}

// restricted softmax-aggregation: dst from list (0=list2, 1=list3, 2=ctx[+out])
__global__ void k_hopl(int lsel, const float* __restrict__ gbias,
                       float* __restrict__ out) {
    int wi = (blockIdx.x * blockDim.x + threadIdx.x) >> 5;
    int lane = threadIdx.x & 31;
    int cnt = (lsel == 0) ? g_cnt2 : (lsel == 1) ? g_cnt3 : Bq;
    if (wi >= cnt) return;
    int w = (lsel == 0) ? g_list2[wi] : (lsel == 1) ? g_list3[wi] : g_ctxn[wi];

    int s = g_off[w], e = g_off[w + 1];
    float adn = g_ad[w];
    float aself = g_as[w] + adn + g_loop[w];
    aself = aself >= 0.f ? aself : 0.2f * aself;
    float m = aself;
    for (int i = s + lane; i < e; i += 32) {
        float a = g_as[g_csrc[i]] + adn + g_cae[i];
        a = a >= 0.f ? a : 0.2f * a;
        m = fmaxf(m, a);
    }
    for (int o = 16; o; o >>= 1) m = fmaxf(m, __shfl_xor_sync(0xffffffffu, m, o));

    float eself = __expf(aself - m);
    float s_sum = eself;
    float4 v = ((const float4*)&g_xl[(size_t)w * HID])[lane];
    float4 acc;
    acc.x = eself * v.x; acc.y = eself * v.y; acc.z = eself * v.z; acc.w = eself * v.w;

    for (int i = s; i < e; i++) {
        int src = g_csrc[i];
        float a = g_as[src] + adn + g_cae[i];
        a = a >= 0.f ? a : 0.2f * a;
        float ee = __expf(a - m);
        s_sum += ee;
        float4 u = ((const float4*)&g_xl[(size_t)src * HID])[lane];
        acc.x += ee * u.x; acc.y += ee * u.y; acc.z += ee * u.z; acc.w += ee * u.w;
    }
    float inv = 1.f / s_sum;
    float4 bb = ((const float4*)gbias)[lane];
    float4 o;
    o.x = acc.x * inv + bb.x; o.y = acc.y * inv + bb.y;
    o.z = acc.z * inv + bb.z; o.w = acc.w * inv + bb.w;
    ((float4*)&g_nodes[(size_t)w * HID])[lane] = o;
    if (lsel == 2) ((float4*)&out[(size_t)wi * HID])[lane] = o;
}

extern "C" void kernel_launch(void* const* d_in, const int* in_sizes, int n_in,
                              void* d_out, int out_size) {
    const float* lm    = (const float*)d_in[0];
    const float* ne    = (const float*)d_in[1];
    const void*  ei    = d_in[2];
    const void*  et    = d_in[3];
    const void*  ctxn  = d_in[4];
    const float* Wlm  = (const float*)d_in[5];
    const float* blm  = (const float*)d_in[6];
    const float* Wbil = (const float*)d_in[7];
    const float* bbil = (const float*)d_in[8];
    const float* tab  = (const float*)d_in[9];
    const float* Wgat = (const float*)d_in[10];
    const float* atts = (const float*)d_in[11];
    const float* attd = (const float*)d_in[12];
    const float* Wed  = (const float*)d_in[13];
    const float* atte = (const float*)d_in[14];
    const float* gb   = (const float*)d_in[15];
    float* out = (float*)d_out;

    int E = in_sizes[2] / 2;
    int eb = (E + 255) / 256;
    int nb64 = (NN + 63) / 64;         // 501 (exact)
    int nb32 = (NN + 31) / 32;
    int wb = (NN + 7) / 8;

    k_init<<<1024, 256>>>(ne);
    k_cvt<<<eb, 256>>>(ei, et, ctxn, E);
    k_prep<<<1, 128>>>(Wed, atte, tab);
    k_tmpp<<<dim3(HID, 2), 256>>>(lm, Wbil);     // index 3 -> ncu capture target
    k_mark3<<<eb, 256>>>(E);
    k_scan<<<1, 1024>>>();
    k_mark2<<<eb, 256>>>(E);
    k_fill<<<eb, 256>>>(E);
    k_compact<<<(NN + 255) / 256, 256>>>();
    k_loopdot<<<wb, 256>>>();

    k_ctx<<<Bq, 1024>>>(lm, Wlm, blm);

    // nodes0: per-graph  xg @ tmp[b]^T + b_bil   (8 row-blocks x 64 graphs)
    dim3 g0((NPG + 63) / 64, Bq);
    k_gemmp<<<g0, 256>>>(0, nullptr, NPG, NPG * HID, bbil, nullptr, nullptr);

    // hop 1: full GEMM, aggregate at A2
    k_gemmp<<<dim3(nb64, 1), 256>>>(1, Wgat, NN, 0, nullptr, atts, attd);
    k_hopl<<<wb, 256>>>(0, gb, nullptr);

    // hop 2: GEMM over A2, aggregate at A3
    k_gemml<<<nb32, 256>>>(0, Wgat, atts, attd);
    k_hopl<<<wb, 256>>>(1, gb, nullptr);

    // hop 3: GEMM over A3, aggregate at ctx (+ output)
    k_gemml<<<nb32, 256>>>(1, Wgat, atts, attd);
    k_hopl<<<(Bq + 7) / 8, 256>>>(2, gb, out);
}

// round 8
// speedup vs baseline: 1.1767x; 1.1767x over previous
#include <cuda_runtime.h>

#define Bq   64
#define NPG  501
#define NN   (Bq * NPG)        // 32064
#define HID  128
#define LMD  1024
#define NREL 42
#define EMAX 520001
#define NPAD (NN + 128)

// ---------------- packed f32x2 helpers (Blackwell FFMA2) ----------------
__device__ __forceinline__ void ffma2(unsigned long long& acc,
                                      unsigned long long a, unsigned long long b) {
    asm("fma.rn.f32x2 %0, %1, %2, %0;" : "+l"(acc) : "l"(a), "l"(b));
}
__device__ __forceinline__ unsigned long long pack2(float x) {
    unsigned long long r;
    asm("mov.b64 %0, {%1, %1};" : "=l"(r) : "f"(x));
    return r;
}
__device__ __forceinline__ float2 unpack2(unsigned long long v) {
    float2 f;
    asm("mov.b64 {%0, %1}, %2;" : "=f"(f.x), "=f"(f.y) : "l"(v));
    return f;
}

// ---------------- scratch (device globals; no allocs) ----------------
__device__ int   g_src[EMAX];
__device__ int   g_dst[EMAX];
__device__ int   g_etype[EMAX];
__device__ int   g_ctxn[Bq];
__device__ float g_ctx[Bq * HID];
__device__ float g_tdot[NREL];
__device__ float g_tmpT[Bq * HID * HID];      // [b][h][k]
__device__ float g_x[NPAD * HID];
__device__ float g_nodes[NPAD * HID];
__device__ float g_xl[NPAD * HID];
__device__ float g_as[NPAD];
__device__ float g_ad[NPAD];
__device__ float g_loop[NN];
__device__ int   g_deg[NN];
__device__ int   g_off[NN + 1];
__device__ int   g_pos[NN];
__device__ int   g_csrc[EMAX];
__device__ float g_cae[EMAX];
// active-set pruning
__device__ int   g_isctx[NN];
__device__ int   g_m3[NN];
__device__ int   g_m2[NN];
__device__ int   g_list2[NN];
__device__ int   g_list3[NN];
__device__ int   g_cnt2;
__device__ int   g_cnt3;

// zero scratch + copy node_emb -> g_x (vectorized)
__global__ void k_init(const float* __restrict__ ne) {
    int i = blockIdx.x * blockDim.x + threadIdx.x;
    int stride = gridDim.x * blockDim.x;
    const float4* s4 = (const float4*)ne;
    float4* d4 = (float4*)g_x;
    for (int j = i; j < NN * HID / 4; j += stride) d4[j] = s4[j];
    for (int j = i; j < NN; j += stride) {
        g_deg[j] = 0; g_isctx[j] = 0; g_m3[j] = 0; g_m2[j] = 0;
    }
    if (i == 0) { g_cnt2 = 0; g_cnt3 = 0; }
}

// cvt (dtype-flexible) + degree atomics + ctx marks, all in one pass
__global__ void k_cvt(const void* __restrict__ ei, const void* __restrict__ et,
                      const void* __restrict__ ctxn, int E) {
    int i = blockIdx.x * blockDim.x + threadIdx.x;
    bool is64 = (((const int*)ctxn)[1] == 0);
    if (i < E) {
        int s, d, t;
        if (is64) {
            s = (int)((const long long*)ei)[i];
            d = (int)((const long long*)ei)[E + i];
            t = (int)((const long long*)et)[i];
        } else {
            s = ((const int*)ei)[i];
            d = ((const int*)ei)[E + i];
            t = ((const int*)et)[i];
        }
        g_src[i] = s; g_dst[i] = d; g_etype[i] = t;
        atomicAdd(&g_deg[d], 1);
    }
    if (i < Bq) {
        int n = is64 ? (int)((const long long*)ctxn)[i] : ((const int*)ctxn)[i];
        g_ctxn[i] = n;
        g_isctx[n] = 1;
        g_m3[n] = 1;
    }
}

// v_edge = W_edge@att_edge; table_dot (MUST precede k_fill)
__global__ void k_prep(const float* __restrict__ We, const float* __restrict__ ae,
                       const float* __restrict__ tab) {
    __shared__ float sv[HID];
    int t = threadIdx.x;
    float acc = 0.f;
    for (int j = 0; j < HID; j++) acc += We[t * HID + j] * ae[j];
    sv[t] = acc;
    __syncthreads();
    if (t < NREL) {
        float a2 = 0.f;
        for (int j = 0; j < HID; j++) a2 += tab[t * HID + j] * sv[j];
        g_tdot[t] = a2;
    }
}

// tmpT[b][h][k] = sum_l lm[b,l]*W_bil[k,l,h]
// grid (128 k, 4 h-quarters); 256 thr: tr=t>>3 -> 2 b rows, tc=t&7 -> 4 h cols.
// lm tile staged in smem (transposed access, padded stride); W streamed once.
__global__ void __launch_bounds__(256) k_tmpp(const float* __restrict__ lm,
                                              const float* __restrict__ Wb) {
    __shared__ float sml[64 * 132];              // 64 b rows x 128 l (pad 132)
    const int k = blockIdx.x;
    const int h0 = blockIdx.y * 32;
    const int t = threadIdx.x;
    const int tc = t & 7, tr = t >> 3;
    const int b0 = tr * 2;
    const int hc = h0 + tc * 4;
    const float* Wk = Wb + (size_t)k * LMD * HID;

    unsigned long long acc[2][2];
    acc[0][0] = acc[0][1] = acc[1][0] = acc[1][1] = 0ull;

    const int bb = t >> 5, lq = t & 31;          // fill mapping
    for (int l0 = 0; l0 < LMD; l0 += 128) {
        __syncthreads();
#pragma unroll
        for (int pass = 0; pass < 8; pass++) {
            int b = bb + pass * 8;
            float4 v = *(const float4*)&lm[(size_t)b * LMD + l0 + lq * 4];
            *(float4*)&sml[b * 132 + lq * 4] = v;
        }
        __syncthreads();

#pragma unroll 8
        for (int l = 0; l < 128; l += 2) {
            float2 a0 = *(const float2*)&sml[b0 * 132 + l];
            float2 a1 = *(const float2*)&sml[(b0 + 1) * 132 + l];
            ulonglong2 w0 = *(const ulonglong2*)&Wk[(size_t)(l0 + l) * HID + hc];
            ulonglong2 w1 = *(const ulonglong2*)&Wk[(size_t)(l0 + l + 1) * HID + hc];
            unsigned long long p;
            p = pack2(a0.x); ffma2(acc[0][0], p, w0.x); ffma2(acc[0][1], p, w0.y);
            p = pack2(a1.x); ffma2(acc[1][0], p, w0.x); ffma2(acc[1][1], p, w0.y);
            p = pack2(a0.y); ffma2(acc[0][0], p, w1.x); ffma2(acc[0][1], p, w1.y);
            p = pack2(a1.y); ffma2(acc[1][0], p, w1.x); ffma2(acc[1][1], p, w1.y);
        }
    }

#pragma unroll
    for (int i = 0; i < 2; i++)
#pragma unroll
        for (int p = 0; p < 2; p++) {
            float2 f = unpack2(acc[i][p]);
            size_t base = (size_t)(b0 + i) * HID * HID + (size_t)(hc + 2 * p) * HID + k;
            g_tmpT[base] = f.x;
            g_tmpT[base + HID] = f.y;
        }
}

__global__ void k_mark3(int E) {
    int i = blockIdx.x * blockDim.x + threadIdx.x;
    if (i < E && g_isctx[g_dst[i]]) g_m3[g_src[i]] = 1;
}

__global__ void k_mark2(int E) {
    int i = blockIdx.x * blockDim.x + threadIdx.x;
    if (i < E && g_m3[g_dst[i]]) g_m2[g_src[i]] = 1;
}

// single-block exclusive scan over g_deg -> g_off, g_pos
__global__ void k_scan() {
    __shared__ int sp[1024];
    int t = threadIdx.x;
    int base = t * 32;
    int loc[32];
    int s = 0;
#pragma unroll
    for (int i = 0; i < 32; i++) {
        int idx = base + i;
        int v = (idx < NN) ? g_deg[idx] : 0;
        loc[i] = s;
        s += v;
    }
    sp[t] = s;
    __syncthreads();
    for (int d = 1; d < 1024; d <<= 1) {
        int v = (t >= d) ? sp[t - d] : 0;
        __syncthreads();
        sp[t] += v;
        __syncthreads();
    }
    int chunk = (t == 0) ? 0 : sp[t - 1];
#pragma unroll
    for (int i = 0; i < 32; i++) {
        int idx = base + i;
        if (idx < NN) {
            int o = chunk + loc[i];
            g_off[idx] = o;
            g_pos[idx] = o;
        }
    }
    if (t == 1023) g_off[NN] = sp[1023];
}

__global__ void k_fill(int E) {
    int i = blockIdx.x * blockDim.x + threadIdx.x;
    if (i < E) {
        int d = g_dst[i];
        int p = atomicAdd(&g_pos[d], 1);
        g_csrc[p] = g_src[i];
        g_cae[p] = g_tdot[g_etype[i]];
    }
}

__global__ void k_compact() {
    int n = blockIdx.x * blockDim.x + threadIdx.x;
    if (n >= NN) return;
    int in3 = g_m3[n];
    int in2 = g_m2[n] | in3;
    if (in3) g_list3[atomicAdd(&g_cnt3, 1)] = n;
    if (in2) g_list2[atomicAdd(&g_cnt2, 1)] = n;
}

// self-loop attention bias = mean of incoming table_dot
__global__ void k_loopdot() {
    int w = (blockIdx.x * blockDim.x + threadIdx.x) >> 5;
    int lane = threadIdx.x & 31;
    if (w >= NN) return;
    int s = g_off[w], e = g_off[w + 1];
    float acc = 0.f;
    for (int i = s + lane; i < e; i += 32) acc += g_cae[i];
    for (int o = 16; o; o >>= 1) acc += __shfl_xor_sync(0xffffffffu, acc, o);
    if (lane == 0) {
        int d = e - s;
        g_loop[w] = d ? acc / (float)d : 0.f;
    }
}

// ctx_emb = lm @ W_lm + b_lm ; writes g_ctx and ctx rows of g_x
__global__ void __launch_bounds__(1024) k_ctx(const float* __restrict__ lm,
                                              const float* __restrict__ W,
                                              const float* __restrict__ bl) {
    __shared__ float red[1024];
    int b = blockIdx.x, t = threadIdx.x;
    int c = t & 127, lg = t >> 7;
    const float* l0 = lm + (size_t)b * LMD + lg * 128;
    const float* Wp = W + (size_t)(lg * 128) * HID + c;
    float a0 = 0.f, a1 = 0.f;
#pragma unroll 8
    for (int l = 0; l < 128; l += 2) {
        a0 += l0[l] * Wp[(size_t)l * HID];
        a1 += l0[l + 1] * Wp[(size_t)(l + 1) * HID];
    }
    red[t] = a0 + a1;
    __syncthreads();
    for (int s = 512; s >= 128; s >>= 1) {
        if (t < s) red[t] += red[t + s];
        __syncthreads();
    }
    if (t < 128) {
        float v = red[t] + bl[t];
        g_ctx[b * HID + t] = v;
        g_x[(size_t)g_ctxn[b] * HID + t] = v;
    }
}

// ===== packed f32x2 GEMM: 64-row block, 4x8 tile/thread =====
__global__ void __launch_bounds__(256) k_gemmp(int mode, const float* __restrict__ Bext,
                                               int M, int sA,
                                               const float* __restrict__ bias,
                                               const float* __restrict__ atts,
                                               const float* __restrict__ attd) {
    __shared__ float Bs[64 * 128];      // 32 KB (K staged in 2 chunks)
    const float* A = mode ? g_nodes : g_x;
    float* C = mode ? g_xl : g_nodes;
    const float* Bm = mode ? Bext : (g_tmpT + (size_t)blockIdx.y * HID * HID);
    A += (size_t)blockIdx.y * sA;
    C += (size_t)blockIdx.y * sA;

    const int t = threadIdx.x;
    const int tc = t & 15, tr = t >> 4;
    const int r0 = blockIdx.x * 64 + tr * 4;
    const int c0 = tc * 8;

    unsigned long long acc2[4][4];
#pragma unroll
    for (int i = 0; i < 4; i++)
#pragma unroll
        for (int p = 0; p < 4; p++) acc2[i][p] = 0ull;

#pragma unroll
    for (int hb = 0; hb < 2; hb++) {
        {
            const float4* src = (const float4*)(Bm + hb * 64 * HID);
            float4* dst = (float4*)Bs;
#pragma unroll
            for (int j = 0; j < 8; j++) dst[t + j * 256] = src[t + j * 256];
        }
        __syncthreads();

#pragma unroll 2
        for (int h4 = 0; h4 < 16; h4++) {
            float4 av[4];
#pragma unroll
            for (int i = 0; i < 4; i++)
                av[i] = *(const float4*)&A[(size_t)(r0 + i) * HID + hb * 64 + h4 * 4];
#pragma unroll
            for (int u = 0; u < 4; u++) {
                ulonglong2 b01 = *(const ulonglong2*)&Bs[(h4 * 4 + u) * 128 + c0];
                ulonglong2 b23 = *(const ulonglong2*)&Bs[(h4 * 4 + u) * 128 + c0 + 4];
#pragma unroll
                for (int i = 0; i < 4; i++) {
                    float a = (u == 0) ? av[i].x : (u == 1) ? av[i].y
                            : (u == 2) ? av[i].z : av[i].w;
                    unsigned long long a2 = pack2(a);
                    ffma2(acc2[i][0], a2, b01.x);
                    ffma2(acc2[i][1], a2, b01.y);
                    ffma2(acc2[i][2], a2, b23.x);
                    ffma2(acc2[i][3], a2, b23.y);
                }
            }
        }
        __syncthreads();
    }

    float accf[4][8];
#pragma unroll
    for (int i = 0; i < 4; i++)
#pragma unroll
        for (int p = 0; p < 4; p++) {
            float2 f = unpack2(acc2[i][p]);
            accf[i][2 * p] = f.x;
            accf[i][2 * p + 1] = f.y;
        }

    float4 bs0 = {0, 0, 0, 0}, bs1 = {0, 0, 0, 0};
    if (bias) {
        bs0 = *(const float4*)&bias[c0];
        bs1 = *(const float4*)&bias[c0 + 4];
    }
#pragma unroll
    for (int i = 0; i < 4; i++) {
        int m = r0 + i;
        if (m < M) {
            float4 w0, w1;
            w0.x = accf[i][0] + bs0.x; w0.y = accf[i][1] + bs0.y;
            w0.z = accf[i][2] + bs0.z; w0.w = accf[i][3] + bs0.w;
            w1.x = accf[i][4] + bs1.x; w1.y = accf[i][5] + bs1.y;
            w1.z = accf[i][6] + bs1.z; w1.w = accf[i][7] + bs1.w;
            *(float4*)&C[(size_t)m * HID + c0] = w0;
            *(float4*)&C[(size_t)m * HID + c0 + 4] = w1;
        }
    }

    if (atts) {
        float4 sa0 = *(const float4*)&atts[c0];
        float4 sa1 = *(const float4*)&atts[c0 + 4];
        float4 da0 = *(const float4*)&attd[c0];
        float4 da1 = *(const float4*)&attd[c0 + 4];
#pragma unroll
        for (int i = 0; i < 4; i++) {
            float ps = accf[i][0] * sa0.x + accf[i][1] * sa0.y + accf[i][2] * sa0.z + accf[i][3] * sa0.w
                     + accf[i][4] * sa1.x + accf[i][5] * sa1.y + accf[i][6] * sa1.z + accf[i][7] * sa1.w;
            float pd = accf[i][0] * da0.x + accf[i][1] * da0.y + accf[i][2] * da0.z + accf[i][3] * da0.w
                     + accf[i][4] * da1.x + accf[i][5] * da1.y + accf[i][6] * da1.z + accf[i][7] * da1.w;
            for (int o = 8; o; o >>= 1) {
                ps += __shfl_down_sync(0xffffffffu, ps, o, 16);
                pd += __shfl_down_sync(0xffffffffu, pd, o, 16);
            }
            int m = r0 + i;
            if (tc == 0 && m < M) { g_as[m] = ps; g_ad[m] = pd; }
        }
    }
}

// 32-row list-indirected GEMM: rows from g_list2 (0) / g_list3 (1)
__global__ void __launch_bounds__(256) k_gemml(int lsel, const float* __restrict__ Bm,
                                               const float* __restrict__ atts,
                                               const float* __restrict__ attd) {
    int cnt = lsel ? g_cnt3 : g_cnt2;
    if (blockIdx.x * 32 >= cnt) return;
    const int* list = lsel ? g_list3 : g_list2;

    int t = threadIdx.x;
    int rg = t >> 3, cg = t & 7;
    int m = blockIdx.x * 32 + rg;
    int k0 = cg * 16;

    bool ok = m < cnt;
    int row = ok ? list[m] : list[0];

    float acc[16];
#pragma unroll
    for (int j = 0; j < 16; j++) acc[j] = 0.f;

    for (int h = 0; h < HID; h += 4) {
        float4 v = *(const float4*)&g_nodes[(size_t)row * HID + h];
        float a[4] = {v.x, v.y, v.z, v.w};
#pragma unroll
        for (int u = 0; u < 4; u++) {
            float br[16];
#pragma unroll
            for (int q = 0; q < 4; q++) {
                float4 w = *(const float4*)&Bm[(size_t)(h + u) * HID + k0 + q * 4];
                br[q * 4 + 0] = w.x; br[q * 4 + 1] = w.y;
                br[q * 4 + 2] = w.z; br[q * 4 + 3] = w.w;
            }
            float av = a[u];
#pragma unroll
            for (int j = 0; j < 16; j++) acc[j] += av * br[j];
        }
    }

    if (ok) {
#pragma unroll
        for (int q = 0; q < 4; q++) {
            float4 w;
            w.x = acc[q * 4 + 0]; w.y = acc[q * 4 + 1];
            w.z = acc[q * 4 + 2]; w.w = acc[q * 4 + 3];
            *(float4*)&g_xl[(size_t)row * HID + k0 + q * 4] = w;
        }
    }

    float ps = 0.f, pd = 0.f;
#pragma unroll
    for (int q = 0; q < 4; q++) {
        float4 w = *(const float4*)&atts[k0 + q * 4];
        float4 u = *(const float4*)&attd[k0 + q * 4];
        ps += acc[q * 4 + 0] * w.x + acc[q * 4 + 1] * w.y + acc[q * 4 + 2] * w.z + acc[q * 4 + 3] * w.w;
        pd += acc[q * 4 + 0] * u.x + acc[q * 4 + 1] * u.y + acc[q * 4 + 2] * u.z + acc[q * 4 + 3] * u.w;
    }
    for (int o = 4; o; o >>= 1) {
        ps += __shfl_down_sync(0xffffffffu, ps, o, 8);
        pd += __shfl_down_sync(0xffffffffu, pd, o, 8);
    }
    if (cg == 0 && ok) { g_as[row] = ps; g_ad[row] = pd; }
}

// restricted softmax-aggregation: dst from list (0=list2, 1=list3, 2=ctx[+out])
__global__ void k_hopl(int lsel, const float* __restrict__ gbias,
                       float* __restrict__ out) {
    int wi = (blockIdx.x * blockDim.x + threadIdx.x) >> 5;
    int lane = threadIdx.x & 31;
    int cnt = (lsel == 0) ? g_cnt2 : (lsel == 1) ? g_cnt3 : Bq;
    if (wi >= cnt) return;
    int w = (lsel == 0) ? g_list2[wi] : (lsel == 1) ? g_list3[wi] : g_ctxn[wi];

    int s = g_off[w], e = g_off[w + 1];
    float adn = g_ad[w];
    float aself = g_as[w] + adn + g_loop[w];
    aself = aself >= 0.f ? aself : 0.2f * aself;
    float m = aself;
    for (int i = s + lane; i < e; i += 32) {
        float a = g_as[g_csrc[i]] + adn + g_cae[i];
        a = a >= 0.f ? a : 0.2f * a;
        m = fmaxf(m, a);
    }
    for (int o = 16; o; o >>= 1) m = fmaxf(m, __shfl_xor_sync(0xffffffffu, m, o));

    float eself = __expf(aself - m);
    float s_sum = eself;
    float4 v = ((const float4*)&g_xl[(size_t)w * HID])[lane];
    float4 acc;
    acc.x = eself * v.x; acc.y = eself * v.y; acc.z = eself * v.z; acc.w = eself * v.w;

    for (int i = s; i < e; i++) {
        int src = g_csrc[i];
        float a = g_as[src] + adn + g_cae[i];
        a = a >= 0.f ? a : 0.2f * a;
        float ee = __expf(a - m);
        s_sum += ee;
        float4 u = ((const float4*)&g_xl[(size_t)src * HID])[lane];
        acc.x += ee * u.x; acc.y += ee * u.y; acc.z += ee * u.z; acc.w += ee * u.w;
    }
    float inv = 1.f / s_sum;
    float4 bb = ((const float4*)gbias)[lane];
    float4 o;
    o.x = acc.x * inv + bb.x; o.y = acc.y * inv + bb.y;
    o.z = acc.z * inv + bb.z; o.w = acc.w * inv + bb.w;
    ((float4*)&g_nodes[(size_t)w * HID])[lane] = o;
    if (lsel == 2) ((float4*)&out[(size_t)wi * HID])[lane] = o;
}

extern "C" void kernel_launch(void* const* d_in, const int* in_sizes, int n_in,
                              void* d_out, int out_size) {
    const float* lm    = (const float*)d_in[0];
    const float* ne    = (const float*)d_in[1];
    const void*  ei    = d_in[2];
    const void*  et    = d_in[3];
    const void*  ctxn  = d_in[4];
    const float* Wlm  = (const float*)d_in[5];
    const float* blm  = (const float*)d_in[6];
    const float* Wbil = (const float*)d_in[7];
    const float* bbil = (const float*)d_in[8];
    const float* tab  = (const float*)d_in[9];
    const float* Wgat = (const float*)d_in[10];
    const float* atts = (const float*)d_in[11];
    const float* attd = (const float*)d_in[12];
    const float* Wed  = (const float*)d_in[13];
    const float* atte = (const float*)d_in[14];
    const float* gb   = (const float*)d_in[15];
    float* out = (float*)d_out;

    int E = in_sizes[2] / 2;
    int eb = (E + 255) / 256;
    int nb64 = (NN + 63) / 64;
    int nb32 = (NN + 31) / 32;
    int wb = (NN + 7) / 8;

    k_init<<<1024, 256>>>(ne);
    k_cvt<<<eb, 256>>>(ei, et, ctxn, E);
    k_prep<<<1, 128>>>(Wed, atte, tab);
    k_tmpp<<<dim3(HID, 4), 256>>>(lm, Wbil);     // 4th launch -> ncu target
    k_mark3<<<eb, 256>>>(E);
    k_scan<<<1, 1024>>>();
    k_mark2<<<eb, 256>>>(E);
    k_fill<<<eb, 256>>>(E);
    k_compact<<<(NN + 255) / 256, 256>>>();
    k_loopdot<<<wb, 256>>>();

    k_ctx<<<Bq, 1024>>>(lm, Wlm, blm);

    // nodes0: per-graph  xg @ tmp[b]^T + b_bil
    dim3 g0((NPG + 63) / 64, Bq);
    k_gemmp<<<g0, 256>>>(0, nullptr, NPG, NPG * HID, bbil, nullptr, nullptr);

    // hop 1: full GEMM, aggregate at A2
    k_gemmp<<<dim3(nb64, 1), 256>>>(1, Wgat, NN, 0, nullptr, atts, attd);
    k_hopl<<<wb, 256>>>(0, gb, nullptr);

    // hop 2: GEMM over A2, aggregate at A3
    k_gemml<<<nb32, 256>>>(0, Wgat, atts, attd);
    k_hopl<<<wb, 256>>>(1, gb, nullptr);

    // hop 3: GEMM over A3, aggregate at ctx (+ output)
    k_gemml<<<nb32, 256>>>(1, Wgat, atts, attd);
    k_hopl<<<(Bq + 7) / 8, 256>>>(2, gb, out);
}

// round 9
// speedup vs baseline: 1.3739x; 1.1676x over previous
#include <cuda_runtime.h>

#define Bq   64
#define NPG  501
#define NN   (Bq * NPG)        // 32064
#define HID  128
#define LMD  1024
#define NREL 42
#define EMAX 520001
#define NPAD (NN + 128)

// ---------------- packed f32x2 helpers (Blackwell FFMA2) ----------------
__device__ __forceinline__ void ffma2(unsigned long long& acc,
                                      unsigned long long a, unsigned long long b) {
    asm("fma.rn.f32x2 %0, %1, %2, %0;" : "+l"(acc) : "l"(a), "l"(b));
}
__device__ __forceinline__ unsigned long long pack2(float x) {
    unsigned long long r;
    asm("mov.b64 %0, {%1, %1};" : "=l"(r) : "f"(x));
    return r;
}
__device__ __forceinline__ float2 unpack2(unsigned long long v) {
    float2 f;
    asm("mov.b64 {%0, %1}, %2;" : "=f"(f.x), "=f"(f.y) : "l"(v));
    return f;
}

// ---------------- scratch (device globals; no allocs) ----------------
__device__ int   g_src[EMAX];
__device__ int   g_dst[EMAX];
__device__ int   g_etype[EMAX];
__device__ int   g_ctxn[Bq];
__device__ float g_ctx[Bq * HID];
__device__ float g_tdot[NREL];
__device__ float g_tmpT[Bq * HID * HID];      // [b][h][k]
__device__ float g_x[NPAD * HID];
__device__ float g_nodes[NPAD * HID];
__device__ float g_xl[NPAD * HID];
__device__ float g_as[NPAD];
__device__ float g_ad[NPAD];
__device__ float g_loop[NN];
__device__ int   g_deg[NN];
__device__ int   g_off[NN + 1];
__device__ int   g_pos[NN];
__device__ int   g_csrc[EMAX];
__device__ float g_cae[EMAX];
// active-set pruning
__device__ int   g_isctx[NN];
__device__ int   g_m3[NN];
__device__ int   g_m2[NN];
__device__ int   g_list2[NN];
__device__ int   g_list3[NN];
__device__ int   g_cnt2;
__device__ int   g_cnt3;

// zero scratch + copy node_emb -> g_x (vectorized)
__global__ void k_init(const float* __restrict__ ne) {
    int i = blockIdx.x * blockDim.x + threadIdx.x;
    int stride = gridDim.x * blockDim.x;
    const float4* s4 = (const float4*)ne;
    float4* d4 = (float4*)g_x;
    for (int j = i; j < NN * HID / 4; j += stride) d4[j] = s4[j];
    for (int j = i; j < NN; j += stride) {
        g_deg[j] = 0; g_isctx[j] = 0; g_m3[j] = 0; g_m2[j] = 0;
    }
    if (i == 0) { g_cnt2 = 0; g_cnt3 = 0; }
}

// cvt (dtype-flexible) + degree atomics + ctx marks, all in one pass
__global__ void k_cvt(const void* __restrict__ ei, const void* __restrict__ et,
                      const void* __restrict__ ctxn, int E) {
    int i = blockIdx.x * blockDim.x + threadIdx.x;
    bool is64 = (((const int*)ctxn)[1] == 0);
    if (i < E) {
        int s, d, t;
        if (is64) {
            s = (int)((const long long*)ei)[i];
            d = (int)((const long long*)ei)[E + i];
            t = (int)((const long long*)et)[i];
        } else {
            s = ((const int*)ei)[i];
            d = ((const int*)ei)[E + i];
            t = ((const int*)et)[i];
        }
        g_src[i] = s; g_dst[i] = d; g_etype[i] = t;
        atomicAdd(&g_deg[d], 1);
    }
    if (i < Bq) {
        int n = is64 ? (int)((const long long*)ctxn)[i] : ((const int*)ctxn)[i];
        g_ctxn[i] = n;
        g_isctx[n] = 1;
        g_m3[n] = 1;
    }
}

// v_edge = W_edge@att_edge; table_dot (MUST precede k_fill)
__global__ void k_prep(const float* __restrict__ We, const float* __restrict__ ae,
                       const float* __restrict__ tab) {
    __shared__ float sv[HID];
    int t = threadIdx.x;
    float acc = 0.f;
    for (int j = 0; j < HID; j++) acc += We[t * HID + j] * ae[j];
    sv[t] = acc;
    __syncthreads();
    if (t < NREL) {
        float a2 = 0.f;
        for (int j = 0; j < HID; j++) a2 += tab[t * HID + j] * sv[j];
        g_tdot[t] = a2;
    }
}

// tmpT[b][h][k] = sum_l lm[b,l]*W_bil[k,l,h]
// grid (128 k, 2 h-halves of 64). Double-buffered smem pipeline:
// W chunk (32l x 64h) + lm chunk (64b x 32l, pad 36) staged per chunk;
// prefetch chunk c+1 into regs during compute of chunk c.
// Thread: tr=t>>3 -> 2 b rows, tc=t&7 -> h cols {tc*4..+3} and {32+tc*4..+3}.
__global__ void __launch_bounds__(256) k_tmpp(const float* __restrict__ lm,
                                              const float* __restrict__ Wb) {
    __shared__ float sW[2][32 * 64];     // 8 KB per buffer
    __shared__ float sA[2][64 * 36];     // 9 KB per buffer (stride 36)
    const int k = blockIdx.x;
    const int h0 = blockIdx.y * 64;
    const int t = threadIdx.x;
    const int tc = t & 7, tr = t >> 3;
    const int b0 = tr * 2;
    const int hw = tc * 4;
    const float* Wk = Wb + (size_t)k * LMD * HID;

    // fill mappings
    const int wl = t >> 3;            // 0..31  (W row within chunk)
    const int wq = (t & 7) * 8;       // col base, 2 float4 per thread
    const int ab = t >> 2;            // 0..63  (lm row)
    const int al = (t & 3) * 8;       // l base, 2 float4 per thread

    unsigned long long acc[2][4];
#pragma unroll
    for (int i = 0; i < 2; i++)
#pragma unroll
        for (int p = 0; p < 4; p++) acc[i][p] = 0ull;

    // prefetch + store chunk 0
    float4 pw0 = *(const float4*)&Wk[(size_t)wl * HID + h0 + wq];
    float4 pw1 = *(const float4*)&Wk[(size_t)wl * HID + h0 + wq + 4];
    float4 pa0 = *(const float4*)&lm[(size_t)ab * LMD + al];
    float4 pa1 = *(const float4*)&lm[(size_t)ab * LMD + al + 4];
    *(float4*)&sW[0][wl * 64 + wq] = pw0;
    *(float4*)&sW[0][wl * 64 + wq + 4] = pw1;
    *(float4*)&sA[0][ab * 36 + al] = pa0;
    *(float4*)&sA[0][ab * 36 + al + 4] = pa1;
    __syncthreads();

    for (int c = 0; c < 32; c++) {
        if (c < 31) {                       // prefetch next chunk (latency hidden)
            int l0 = (c + 1) * 32;
            pw0 = *(const float4*)&Wk[(size_t)(l0 + wl) * HID + h0 + wq];
            pw1 = *(const float4*)&Wk[(size_t)(l0 + wl) * HID + h0 + wq + 4];
            pa0 = *(const float4*)&lm[(size_t)ab * LMD + l0 + al];
            pa1 = *(const float4*)&lm[(size_t)ab * LMD + l0 + al + 4];
        }
        const float* cW = sW[c & 1];
        const float* cA = sA[c & 1];
#pragma unroll
        for (int l = 0; l < 32; l += 2) {
            float2 a0 = *(const float2*)&cA[b0 * 36 + l];
            float2 a1 = *(const float2*)&cA[(b0 + 1) * 36 + l];
            ulonglong2 w0a = *(const ulonglong2*)&cW[l * 64 + hw];
            ulonglong2 w0b = *(const ulonglong2*)&cW[l * 64 + 32 + hw];
            ulonglong2 w1a = *(const ulonglong2*)&cW[(l + 1) * 64 + hw];
            ulonglong2 w1b = *(const ulonglong2*)&cW[(l + 1) * 64 + 32 + hw];
            unsigned long long p;
            p = pack2(a0.x);
            ffma2(acc[0][0], p, w0a.x); ffma2(acc[0][1], p, w0a.y);
            ffma2(acc[0][2], p, w0b.x); ffma2(acc[0][3], p, w0b.y);
            p = pack2(a1.x);
            ffma2(acc[1][0], p, w0a.x); ffma2(acc[1][1], p, w0a.y);
            ffma2(acc[1][2], p, w0b.x); ffma2(acc[1][3], p, w0b.y);
            p = pack2(a0.y);
            ffma2(acc[0][0], p, w1a.x); ffma2(acc[0][1], p, w1a.y);
            ffma2(acc[0][2], p, w1b.x); ffma2(acc[0][3], p, w1b.y);
            p = pack2(a1.y);
            ffma2(acc[1][0], p, w1a.x); ffma2(acc[1][1], p, w1a.y);
            ffma2(acc[1][2], p, w1b.x); ffma2(acc[1][3], p, w1b.y);
        }
        __syncthreads();
        if (c < 31) {
            int nb = (c + 1) & 1;
            *(float4*)&sW[nb][wl * 64 + wq] = pw0;
            *(float4*)&sW[nb][wl * 64 + wq + 4] = pw1;
            *(float4*)&sA[nb][ab * 36 + al] = pa0;
            *(float4*)&sA[nb][ab * 36 + al + 4] = pa1;
        }
        __syncthreads();
    }

    // store: acc[i][0..1] -> h0+hw+{0..3}; acc[i][2..3] -> h0+32+hw+{0..3}
#pragma unroll
    for (int i = 0; i < 2; i++) {
        size_t bb = (size_t)(b0 + i) * HID * HID + k;
#pragma unroll
        for (int p = 0; p < 4; p++) {
            float2 f = unpack2(acc[i][p]);
            int h = (p < 2) ? (h0 + hw + 2 * p) : (h0 + 32 + hw + 2 * (p - 2));
            g_tmpT[bb + (size_t)h * HID] = f.x;
            g_tmpT[bb + (size_t)(h + 1) * HID] = f.y;
        }
    }
}

__global__ void k_mark3(int E) {
    int i = blockIdx.x * blockDim.x + threadIdx.x;
    if (i < E && g_isctx[g_dst[i]]) g_m3[g_src[i]] = 1;
}

__global__ void k_mark2(int E) {
    int i = blockIdx.x * blockDim.x + threadIdx.x;
    if (i < E && g_m3[g_dst[i]]) g_m2[g_src[i]] = 1;
}

// single-block exclusive scan over g_deg -> g_off, g_pos
__global__ void k_scan() {
    __shared__ int sp[1024];
    int t = threadIdx.x;
    int base = t * 32;
    int loc[32];
    int s = 0;
#pragma unroll
    for (int i = 0; i < 32; i++) {
        int idx = base + i;
        int v = (idx < NN) ? g_deg[idx] : 0;
        loc[i] = s;
        s += v;
    }
    sp[t] = s;
    __syncthreads();
    for (int d = 1; d < 1024; d <<= 1) {
        int v = (t >= d) ? sp[t - d] : 0;
        __syncthreads();
        sp[t] += v;
        __syncthreads();
    }
    int chunk = (t == 0) ? 0 : sp[t - 1];
#pragma unroll
    for (int i = 0; i < 32; i++) {
        int idx = base + i;
        if (idx < NN) {
            int o = chunk + loc[i];
            g_off[idx] = o;
            g_pos[idx] = o;
        }
    }
    if (t == 1023) g_off[NN] = sp[1023];
}

__global__ void k_fill(int E) {
    int i = blockIdx.x * blockDim.x + threadIdx.x;
    if (i < E) {
        int d = g_dst[i];
        int p = atomicAdd(&g_pos[d], 1);
        g_csrc[p] = g_src[i];
        g_cae[p] = g_tdot[g_etype[i]];
    }
}

__global__ void k_compact() {
    int n = blockIdx.x * blockDim.x + threadIdx.x;
    if (n >= NN) return;
    int in3 = g_m3[n];
    int in2 = g_m2[n] | in3;
    if (in3) g_list3[atomicAdd(&g_cnt3, 1)] = n;
    if (in2) g_list2[atomicAdd(&g_cnt2, 1)] = n;
}

// self-loop attention bias = mean of incoming table_dot
__global__ void k_loopdot() {
    int w = (blockIdx.x * blockDim.x + threadIdx.x) >> 5;
    int lane = threadIdx.x & 31;
    if (w >= NN) return;
    int s = g_off[w], e = g_off[w + 1];
    float acc = 0.f;
    for (int i = s + lane; i < e; i += 32) acc += g_cae[i];
    for (int o = 16; o; o >>= 1) acc += __shfl_xor_sync(0xffffffffu, acc, o);
    if (lane == 0) {
        int d = e - s;
        g_loop[w] = d ? acc / (float)d : 0.f;
    }
}

// ctx_emb = lm @ W_lm + b_lm ; writes g_ctx and ctx rows of g_x
__global__ void __launch_bounds__(1024) k_ctx(const float* __restrict__ lm,
                                              const float* __restrict__ W,
                                              const float* __restrict__ bl) {
    __shared__ float red[1024];
    int b = blockIdx.x, t = threadIdx.x;
    int c = t & 127, lg = t >> 7;
    const float* l0 = lm + (size_t)b * LMD + lg * 128;
    const float* Wp = W + (size_t)(lg * 128) * HID + c;
    float a0 = 0.f, a1 = 0.f;
#pragma unroll 8
    for (int l = 0; l < 128; l += 2) {
        a0 += l0[l] * Wp[(size_t)l * HID];
        a1 += l0[l + 1] * Wp[(size_t)(l + 1) * HID];
    }
    red[t] = a0 + a1;
    __syncthreads();
    for (int s = 512; s >= 128; s >>= 1) {
        if (t < s) red[t] += red[t + s];
        __syncthreads();
    }
    if (t < 128) {
        float v = red[t] + bl[t];
        g_ctx[b * HID + t] = v;
        g_x[(size_t)g_ctxn[b] * HID + t] = v;
    }
}

// ===== packed f32x2 GEMM: 64-row block, 4x8 tile/thread =====
__global__ void __launch_bounds__(256) k_gemmp(int mode, const float* __restrict__ Bext,
                                               int M, int sA,
                                               const float* __restrict__ bias,
                                               const float* __restrict__ atts,
                                               const float* __restrict__ attd) {
    __shared__ float Bs[64 * 128];      // 32 KB (K staged in 2 chunks)
    const float* A = mode ? g_nodes : g_x;
    float* C = mode ? g_xl : g_nodes;
    const float* Bm = mode ? Bext : (g_tmpT + (size_t)blockIdx.y * HID * HID);
    A += (size_t)blockIdx.y * sA;
    C += (size_t)blockIdx.y * sA;

    const int t = threadIdx.x;
    const int tc = t & 15, tr = t >> 4;
    const int r0 = blockIdx.x * 64 + tr * 4;
    const int c0 = tc * 8;

    unsigned long long acc2[4][4];
#pragma unroll
    for (int i = 0; i < 4; i++)
#pragma unroll
        for (int p = 0; p < 4; p++) acc2[i][p] = 0ull;

#pragma unroll
    for (int hb = 0; hb < 2; hb++) {
        {
            const float4* src = (const float4*)(Bm + hb * 64 * HID);
            float4* dst = (float4*)Bs;
#pragma unroll
            for (int j = 0; j < 8; j++) dst[t + j * 256] = src[t + j * 256];
        }
        __syncthreads();

#pragma unroll 2
        for (int h4 = 0; h4 < 16; h4++) {
            float4 av[4];
#pragma unroll
            for (int i = 0; i < 4; i++)
                av[i] = *(const float4*)&A[(size_t)(r0 + i) * HID + hb * 64 + h4 * 4];
#pragma unroll
            for (int u = 0; u < 4; u++) {
                ulonglong2 b01 = *(const ulonglong2*)&Bs[(h4 * 4 + u) * 128 + c0];
                ulonglong2 b23 = *(const ulonglong2*)&Bs[(h4 * 4 + u) * 128 + c0 + 4];
#pragma unroll
                for (int i = 0; i < 4; i++) {
                    float a = (u == 0) ? av[i].x : (u == 1) ? av[i].y
                            : (u == 2) ? av[i].z : av[i].w;
                    unsigned long long a2 = pack2(a);
                    ffma2(acc2[i][0], a2, b01.x);
                    ffma2(acc2[i][1], a2, b01.y);
                    ffma2(acc2[i][2], a2, b23.x);
                    ffma2(acc2[i][3], a2, b23.y);
                }
            }
        }
        __syncthreads();
    }

    float accf[4][8];
#pragma unroll
    for (int i = 0; i < 4; i++)
#pragma unroll
        for (int p = 0; p < 4; p++) {
            float2 f = unpack2(acc2[i][p]);
            accf[i][2 * p] = f.x;
            accf[i][2 * p + 1] = f.y;
        }

    float4 bs0 = {0, 0, 0, 0}, bs1 = {0, 0, 0, 0};
    if (bias) {
        bs0 = *(const float4*)&bias[c0];
        bs1 = *(const float4*)&bias[c0 + 4];
    }
#pragma unroll
    for (int i = 0; i < 4; i++) {
        int m = r0 + i;
        if (m < M) {
            float4 w0, w1;
            w0.x = accf[i][0] + bs0.x; w0.y = accf[i][1] + bs0.y;
            w0.z = accf[i][2] + bs0.z; w0.w = accf[i][3] + bs0.w;
            w1.x = accf[i][4] + bs1.x; w1.y = accf[i][5] + bs1.y;
            w1.z = accf[i][6] + bs1.z; w1.w = accf[i][7] + bs1.w;
            *(float4*)&C[(size_t)m * HID + c0] = w0;
            *(float4*)&C[(size_t)m * HID + c0 + 4] = w1;
        }
    }

    if (atts) {
        float4 sa0 = *(const float4*)&atts[c0];
        float4 sa1 = *(const float4*)&atts[c0 + 4];
        float4 da0 = *(const float4*)&attd[c0];
        float4 da1 = *(const float4*)&attd[c0 + 4];
#pragma unroll
        for (int i = 0; i < 4; i++) {
            float ps = accf[i][0] * sa0.x + accf[i][1] * sa0.y + accf[i][2] * sa0.z + accf[i][3] * sa0.w
                     + accf[i][4] * sa1.x + accf[i][5] * sa1.y + accf[i][6] * sa1.z + accf[i][7] * sa1.w;
            float pd = accf[i][0] * da0.x + accf[i][1] * da0.y + accf[i][2] * da0.z + accf[i][3] * da0.w
                     + accf[i][4] * da1.x + accf[i][5] * da1.y + accf[i][6] * da1.z + accf[i][7] * da1.w;
            for (int o = 8; o; o >>= 1) {
                ps += __shfl_down_sync(0xffffffffu, ps, o, 16);
                pd += __shfl_down_sync(0xffffffffu, pd, o, 16);
            }
            int m = r0 + i;
            if (tc == 0 && m < M) { g_as[m] = ps; g_ad[m] = pd; }
        }
    }
}

// 32-row list-indirected GEMM: rows from g_list2 (0) / g_list3 (1)
__global__ void __launch_bounds__(256) k_gemml(int lsel, const float* __restrict__ Bm,
                                               const float* __restrict__ atts,
                                               const float* __restrict__ attd) {
    int cnt = lsel ? g_cnt3 : g_cnt2;
    if (blockIdx.x * 32 >= cnt) return;
    const int* list = lsel ? g_list3 : g_list2;

    int t = threadIdx.x;
    int rg = t >> 3, cg = t & 7;
    int m = blockIdx.x * 32 + rg;
    int k0 = cg * 16;

    bool ok = m < cnt;
    int row = ok ? list[m] : list[0];

    float acc[16];
#pragma unroll
    for (int j = 0; j < 16; j++) acc[j] = 0.f;

    for (int h = 0; h < HID; h += 4) {
        float4 v = *(const float4*)&g_nodes[(size_t)row * HID + h];
        float a[4] = {v.x, v.y, v.z, v.w};
#pragma unroll
        for (int u = 0; u < 4; u++) {
            float br[16];
#pragma unroll
            for (int q = 0; q < 4; q++) {
                float4 w = *(const float4*)&Bm[(size_t)(h + u) * HID + k0 + q * 4];
                br[q * 4 + 0] = w.x; br[q * 4 + 1] = w.y;
                br[q * 4 + 2] = w.z; br[q * 4 + 3] = w.w;
            }
            float av = a[u];
#pragma unroll
            for (int j = 0; j < 16; j++) acc[j] += av * br[j];
        }
    }

    if (ok) {
#pragma unroll
        for (int q = 0; q < 4; q++) {
            float4 w;
            w.x = acc[q * 4 + 0]; w.y = acc[q * 4 + 1];
            w.z = acc[q * 4 + 2]; w.w = acc[q * 4 + 3];
            *(float4*)&g_xl[(size_t)row * HID + k0 + q * 4] = w;
        }
    }

    float ps = 0.f, pd = 0.f;
#pragma unroll
    for (int q = 0; q < 4; q++) {
        float4 w = *(const float4*)&atts[k0 + q * 4];
        float4 u = *(const float4*)&attd[k0 + q * 4];
        ps += acc[q * 4 + 0] * w.x + acc[q * 4 + 1] * w.y + acc[q * 4 + 2] * w.z + acc[q * 4 + 3] * w.w;
        pd += acc[q * 4 + 0] * u.x + acc[q * 4 + 1] * u.y + acc[q * 4 + 2] * u.z + acc[q * 4 + 3] * u.w;
    }
    for (int o = 4; o; o >>= 1) {
        ps += __shfl_down_sync(0xffffffffu, ps, o, 8);
        pd += __shfl_down_sync(0xffffffffu, pd, o, 8);
    }
    if (cg == 0 && ok) { g_as[row] = ps; g_ad[row] = pd; }
}

// restricted softmax-aggregation: dst from list (0=list2, 1=list3, 2=ctx[+out])
__global__ void k_hopl(int lsel, const float* __restrict__ gbias,
                       float* __restrict__ out) {
    int wi = (blockIdx.x * blockDim.x + threadIdx.x) >> 5;
    int lane = threadIdx.x & 31;
    int cnt = (lsel == 0) ? g_cnt2 : (lsel == 1) ? g_cnt3 : Bq;
    if (wi >= cnt) return;
    int w = (lsel == 0) ? g_list2[wi] : (lsel == 1) ? g_list3[wi] : g_ctxn[wi];

    int s = g_off[w], e = g_off[w + 1];
    float adn = g_ad[w];
    float aself = g_as[w] + adn + g_loop[w];
    aself = aself >= 0.f ? aself : 0.2f * aself;
    float m = aself;
    for (int i = s + lane; i < e; i += 32) {
        float a = g_as[g_csrc[i]] + adn + g_cae[i];
        a = a >= 0.f ? a : 0.2f * a;
        m = fmaxf(m, a);
    }
    for (int o = 16; o; o >>= 1) m = fmaxf(m, __shfl_xor_sync(0xffffffffu, m, o));

    float eself = __expf(aself - m);
    float s_sum = eself;
    float4 v = ((const float4*)&g_xl[(size_t)w * HID])[lane];
    float4 acc;
    acc.x = eself * v.x; acc.y = eself * v.y; acc.z = eself * v.z; acc.w = eself * v.w;

    for (int i = s; i < e; i++) {
        int src = g_csrc[i];
        float a = g_as[src] + adn + g_cae[i];
        a = a >= 0.f ? a : 0.2f * a;
        float ee = __expf(a - m);
        s_sum += ee;
        float4 u = ((const float4*)&g_xl[(size_t)src * HID])[lane];
        acc.x += ee * u.x; acc.y += ee * u.y; acc.z += ee * u.z; acc.w += ee * u.w;
    }
    float inv = 1.f / s_sum;
    float4 bb = ((const float4*)gbias)[lane];
    float4 o;
    o.x = acc.x * inv + bb.x; o.y = acc.y * inv + bb.y;
    o.z = acc.z * inv + bb.z; o.w = acc.w * inv + bb.w;
    ((float4*)&g_nodes[(size_t)w * HID])[lane] = o;
    if (lsel == 2) ((float4*)&out[(size_t)wi * HID])[lane] = o;
}

extern "C" void kernel_launch(void* const* d_in, const int* in_sizes, int n_in,
                              void* d_out, int out_size) {
    const float* lm    = (const float*)d_in[0];
    const float* ne    = (const float*)d_in[1];
    const void*  ei    = d_in[2];
    const void*  et    = d_in[3];
    const void*  ctxn  = d_in[4];
    const float* Wlm  = (const float*)d_in[5];
    const float* blm  = (const float*)d_in[6];
    const float* Wbil = (const float*)d_in[7];
    const float* bbil = (const float*)d_in[8];
    const float* tab  = (const float*)d_in[9];
    const float* Wgat = (const float*)d_in[10];
    const float* atts = (const float*)d_in[11];
    const float* attd = (const float*)d_in[12];
    const float* Wed  = (const float*)d_in[13];
    const float* atte = (const float*)d_in[14];
    const float* gb   = (const float*)d_in[15];
    float* out = (float*)d_out;

    int E = in_sizes[2] / 2;
    int eb = (E + 255) / 256;
    int nb64 = (NN + 63) / 64;
    int nb32 = (NN + 31) / 32;
    int wb = (NN + 7) / 8;

    k_init<<<1024, 256>>>(ne);
    k_cvt<<<eb, 256>>>(ei, et, ctxn, E);
    k_prep<<<1, 128>>>(Wed, atte, tab);
    k_tmpp<<<dim3(HID, 2), 256>>>(lm, Wbil);     // 4th launch -> ncu target
    k_mark3<<<eb, 256>>>(E);
    k_scan<<<1, 1024>>>();
    k_mark2<<<eb, 256>>>(E);
    k_fill<<<eb, 256>>>(E);
    k_compact<<<(NN + 255) / 256, 256>>>();
    k_loopdot<<<wb, 256>>>();

    k_ctx<<<Bq, 1024>>>(lm, Wlm, blm);

    // nodes0: per-graph  xg @ tmp[b]^T + b_bil
    dim3 g0((NPG + 63) / 64, Bq);
    k_gemmp<<<g0, 256>>>(0, nullptr, NPG, NPG * HID, bbil, nullptr, nullptr);

    // hop 1: full GEMM, aggregate at A2
    k_gemmp<<<dim3(nb64, 1), 256>>>(1, Wgat, NN, 0, nullptr, atts, attd);
    k_hopl<<<wb, 256>>>(0, gb, nullptr);

    // hop 2: GEMM over A2, aggregate at A3
    k_gemml<<<nb32, 256>>>(0, Wgat, atts, attd);
    k_hopl<<<wb, 256>>>(1, gb, nullptr);

    // hop 3: GEMM over A3, aggregate at ctx (+ output)
    k_gemml<<<nb32, 256>>>(1, Wgat, atts, attd);
    k_hopl<<<(Bq + 7) / 8, 256>>>(2, gb, out);
}